// round 8
// baseline (speedup 1.0000x reference)
#include <cuda_runtime.h>
#include <cuda_bf16.h>
#include <cstdint>

// ---------------------------------------------------------------------------
// GCN VGAE encoder (fp32, f32x2 FFMA GEMMs 64x128 tile, CSR gather batched 4/warp)
//   dinv = rsqrt(indeg+1)
//   conv: hs = (X@W)*dinv[row]
//         agg[v] = hs[v] + sum_in hs[src]           (CSR gather, 4 nodes/warp)
//         next input = relu(dinv[v]*agg[v] + b)     (fused into consumer GEMM)
//   heads: [mu|lv] = relu(dinv*aggB + b2) @ [Wmu|Wlv] + bias
// ---------------------------------------------------------------------------

#define MAXN 50000
#define MAXE 800000
#define FDIM 128

__device__ float g_dinv[MAXN];
__device__ int   g_degi[MAXN];
__device__ int   g_off [MAXN + 1];
__device__ int   g_cur [MAXN];
__device__ int   g_csr [MAXE];
__device__ int   g_bsum[256];
__device__ float g_hs  [MAXN * FDIM];
__device__ float g_aggA[MAXN * FDIM];
__device__ float g_aggB[MAXN * FDIM];

typedef unsigned long long ull;

#define SPLAT2(d, x) asm("mov.b64 %0, {%1, %1};" : "=l"(d) : "f"(x))
#define FMA2(d, a, b, c) \
    asm("fma.rn.f32x2 %0, %1, %2, %3;" : "=l"(d) : "l"(a), "l"(b), "l"(c))
#define UNPACK2(lo, hi, v) \
    asm("mov.b64 {%0, %1}, %2;" : "=f"(lo), "=f"(hi) : "l"(v))

// ======================= degree + CSR build =======================

__global__ void zero_deg_kernel(int N) {
    int i = blockIdx.x * blockDim.x + threadIdx.x;
    if (i < N) g_degi[i] = 0;
}

__global__ void count_deg_kernel(const int* __restrict__ ei, int E) {
    int e = blockIdx.x * blockDim.x + threadIdx.x;
    if (e < E) atomicAdd(&g_degi[ei[E + e]], 1);
}

__global__ void scan1_kernel(int N) {
    __shared__ int s[256];
    int t = threadIdx.x;
    int i = blockIdx.x * 256 + t;
    s[t] = (i < N) ? g_degi[i] : 0;
    __syncthreads();
#pragma unroll
    for (int d = 128; d > 0; d >>= 1) {
        if (t < d) s[t] += s[t + d];
        __syncthreads();
    }
    if (t == 0) g_bsum[blockIdx.x] = s[0];
}

// per-block scan with redundant block-sum scan -> off, cur, dinv
__global__ void scan3_kernel(int N, int nb) {
    __shared__ int bs[256];
    __shared__ int s[256];
    int t = threadIdx.x;

    int bv = (t < nb) ? g_bsum[t] : 0;
    bs[t] = bv;
    __syncthreads();
#pragma unroll
    for (int d = 1; d < 256; d <<= 1) {
        int v = (t >= d) ? bs[t - d] : 0;
        __syncthreads();
        bs[t] += v;
        __syncthreads();
    }
    int base = bs[blockIdx.x] - ((blockIdx.x < nb) ? g_bsum[blockIdx.x] : 0);

    int i = blockIdx.x * 256 + t;
    int deg = (i < N) ? g_degi[i] : 0;
    s[t] = deg;
    __syncthreads();
#pragma unroll
    for (int d = 1; d < 256; d <<= 1) {
        int v = (t >= d) ? s[t - d] : 0;
        __syncthreads();
        s[t] += v;
        __syncthreads();
    }
    if (i < N) {
        int off = base + s[t] - deg;
        g_off[i] = off;
        g_cur[i] = off;
        g_dinv[i] = rsqrtf((float)deg + 1.0f);
        if (i == N - 1) g_off[N] = off + deg;
    }
}

__global__ void fill_csr_kernel(const int* __restrict__ ei, int E) {
    int e = blockIdx.x * blockDim.x + threadIdx.x;
    if (e < E) {
        int d = ei[E + e];
        int pos = atomicAdd(&g_cur[d], 1);
        g_csr[pos] = ei[e];
    }
}

// ======================= GEMM machinery =======================
// 256 threads, tile 64 rows x 128 cols. tx=t&31 -> cols tx*4..+3 ;
// ty=t>>5 (8 warps) -> rows ty*8..+7. Ws[128][128] + Xs[64][128] = 96KB smem.

#define GEMM_SMEM ((128 * 128 + 64 * 128) * 4)

__device__ __forceinline__ void load_xtile(float* Xs, const float* __restrict__ src,
                                           const float* __restrict__ bias, int fuse,
                                           int rowBase, int N, int t) {
#pragma unroll
    for (int i = 0; i < 8; i++) {
        int idx = t + i * 256;
        int r = idx >> 5, c4 = idx & 31;
        int rg = rowBase + r;
        float4 v = make_float4(0.f, 0.f, 0.f, 0.f);
        if (rg < N) {
            v = ((const float4*)src)[(size_t)rg * 32 + c4];
            if (fuse) {
                float dv = g_dinv[rg];
                float4 bb = ((const float4*)bias)[c4];
                v.x = fmaxf(v.x * dv + bb.x, 0.f);
                v.y = fmaxf(v.y * dv + bb.y, 0.f);
                v.z = fmaxf(v.z * dv + bb.z, 0.f);
                v.w = fmaxf(v.w * dv + bb.w, 0.f);
            }
        }
        ((float4*)Xs)[idx] = v;
    }
}

__device__ __forceinline__ void mm_tile(const float* Ws, const float* Xs,
                                        int c0, int r0, ull acc[8][2]) {
#pragma unroll
    for (int i = 0; i < 8; i++) { acc[i][0] = 0ull; acc[i][1] = 0ull; }

#pragma unroll 2
    for (int k0 = 0; k0 < 128; k0 += 4) {
        float4 a[8];
#pragma unroll
        for (int i = 0; i < 8; i++)
            a[i] = *(const float4*)(Xs + (r0 + i) * 128 + k0);
#pragma unroll
        for (int kk = 0; kk < 4; kk++) {
            ulonglong2 w = *(const ulonglong2*)(Ws + (k0 + kk) * 128 + c0);
#pragma unroll
            for (int i = 0; i < 8; i++) {
                ull s;
                SPLAT2(s, ((const float*)&a[i])[kk]);
                FMA2(acc[i][0], s, w.x, acc[i][0]);
                FMA2(acc[i][1], s, w.y, acc[i][1]);
            }
        }
    }
}

// conv GEMM: hs = (X@W)*dinv. stage0: X=xin raw; stage1: X=relu(dinv*aggA+bias)
__global__ void __launch_bounds__(256)
gemm_conv_kernel(const float* __restrict__ xin,
                 const float* __restrict__ W,
                 const float* __restrict__ bias,
                 int N, int stage) {
    extern __shared__ float sm[];
    float* Ws = sm;
    float* Xs = sm + 128 * 128;
    const int t = threadIdx.x;
    const float* src = (stage == 0) ? xin : (const float*)g_aggA;

#pragma unroll
    for (int i = 0; i < 16; i++) {
        int idx = t + i * 256;
        ((float4*)Ws)[idx] = ((const float4*)W)[idx];
    }
    const int rowBase = blockIdx.x * 64;
    load_xtile(Xs, src, bias, stage != 0, rowBase, N, t);
    __syncthreads();

    const int tx = t & 31, ty = t >> 5;
    const int c0 = tx * 4, r0 = ty * 8;
    ull acc[8][2];
    mm_tile(Ws, Xs, c0, r0, acc);

#pragma unroll
    for (int i = 0; i < 8; i++) {
        int r = rowBase + r0 + i;
        if (r < N) {
            float dv = g_dinv[r];
            float a0, a1, a2, a3;
            UNPACK2(a0, a1, acc[i][0]);
            UNPACK2(a2, a3, acc[i][1]);
            *(float4*)(g_hs + (size_t)r * 128 + c0) =
                make_float4(a0 * dv, a1 * dv, a2 * dv, a3 * dv);
        }
    }
}

// final GEMM: [mu|lv] = relu(dinv*aggB+b2) @ [Wmu|Wlv] + bias
__global__ void __launch_bounds__(256)
gemm_final_kernel(const float* __restrict__ Wmu,
                  const float* __restrict__ Wlv,
                  const float* __restrict__ bmu,
                  const float* __restrict__ blv,
                  const float* __restrict__ b2,
                  float* __restrict__ out,
                  int N) {
    extern __shared__ float sm[];
    float* Ws = sm;
    float* Xs = sm + 128 * 128;
    const int t = threadIdx.x;

#pragma unroll
    for (int i = 0; i < 16; i++) {
        int idx = t + i * 256;
        int k = idx >> 5;
        int cc4 = idx & 31;
        float4 v = (cc4 < 16) ? ((const float4*)Wmu)[k * 16 + cc4]
                              : ((const float4*)Wlv)[k * 16 + (cc4 - 16)];
        ((float4*)Ws)[idx] = v;
    }
    const int rowBase = blockIdx.x * 64;
    load_xtile(Xs, (const float*)g_aggB, b2, 1, rowBase, N, t);
    __syncthreads();

    const int tx = t & 31, ty = t >> 5;
    const int c0 = tx * 4, r0 = ty * 8;
    ull acc[8][2];
    mm_tile(Ws, Xs, c0, r0, acc);

    const bool is_mu = (c0 < 64);
    const int cl = is_mu ? c0 : (c0 - 64);
    float4 bs = is_mu ? *(const float4*)(bmu + cl) : *(const float4*)(blv + cl);
#pragma unroll
    for (int i = 0; i < 8; i++) {
        int r = rowBase + r0 + i;
        if (r < N) {
            float a0, a1, a2, a3;
            UNPACK2(a0, a1, acc[i][0]);
            UNPACK2(a2, a3, acc[i][1]);
            float* base = is_mu ? (out + (size_t)r * 64 + cl)
                                : (out + (size_t)N * 64 + (size_t)r * 64 + cl);
            *(float4*)base = make_float4(a0 + bs.x, a1 + bs.y, a2 + bs.z, a3 + bs.w);
        }
    }
}

// ====== gather: agg[v] = hs[v] + sum_in hs[src]; 4 nodes/warp, interleaved ==

__global__ void gather_kernel(int N, int which) {
    const int w = (blockIdx.x * blockDim.x + threadIdx.x) >> 5;
    const int lane = threadIdx.x & 31;
    const int n0 = w * 4;
    if (n0 >= N) return;
    float* agg = which ? g_aggB : g_aggA;
    const float4* hs4 = (const float4*)g_hs;

    float4 acc[4];
    int j[4], end[4];
#pragma unroll
    for (int q = 0; q < 4; q++) {
        int n = n0 + q;
        if (n < N) {
            acc[q] = hs4[(size_t)n * 32 + lane];   // self-loop seed
            j[q] = g_off[n];
            end[q] = g_off[n + 1];
        } else {
            acc[q] = make_float4(0.f, 0.f, 0.f, 0.f);
            j[q] = 0; end[q] = 0;
        }
    }

    for (;;) {
        bool any = false;
        float4 v[4][2];
        bool p[4][2];
#pragma unroll
        for (int q = 0; q < 4; q++) {
#pragma unroll
            for (int u = 0; u < 2; u++) {
                p[q][u] = (j[q] + u < end[q]);
                if (p[q][u]) {
                    int s = g_csr[j[q] + u];
                    v[q][u] = hs4[(size_t)s * 32 + lane];
                    any = true;
                }
            }
        }
        if (!any) break;   // j/end warp-uniform -> no divergence
#pragma unroll
        for (int q = 0; q < 4; q++) {
#pragma unroll
            for (int u = 0; u < 2; u++) {
                if (p[q][u]) {
                    acc[q].x += v[q][u].x; acc[q].y += v[q][u].y;
                    acc[q].z += v[q][u].z; acc[q].w += v[q][u].w;
                }
            }
            j[q] += 2;
        }
    }

#pragma unroll
    for (int q = 0; q < 4; q++) {
        int n = n0 + q;
        if (n < N) ((float4*)agg)[(size_t)n * 32 + lane] = acc[q];
    }
}

// ======================= launch =======================

extern "C" void kernel_launch(void* const* d_in, const int* in_sizes, int n_in,
                              void* d_out, int out_size) {
    const float* x   = (const float*)d_in[0];
    const int*   ei  = (const int*)d_in[1];      // int32 edge_index [2, E]
    const float* W1  = (const float*)d_in[2];
    const float* b1  = (const float*)d_in[3];
    const float* W2  = (const float*)d_in[4];
    const float* b2  = (const float*)d_in[5];
    const float* Wmu = (const float*)d_in[6];
    const float* bmu = (const float*)d_in[7];
    const float* Wlv = (const float*)d_in[8];
    const float* blv = (const float*)d_in[9];
    float* out = (float*)d_out;

    const int N = in_sizes[0] / 128;
    const int E = in_sizes[1] / 2;

    cudaFuncSetAttribute(gemm_conv_kernel,
                         cudaFuncAttributeMaxDynamicSharedMemorySize, GEMM_SMEM);
    cudaFuncSetAttribute(gemm_final_kernel,
                         cudaFuncAttributeMaxDynamicSharedMemorySize, GEMM_SMEM);

    const int nb = (N + 255) / 256;               // <= 256 for N <= 65536
    const int gemm_blocks = (N + 63) / 64;
    const int gath_blocks = ((N + 3) / 4 + 7) / 8;  // 4 nodes/warp, 8 warps/block

    // degree + CSR
    zero_deg_kernel<<<nb, 256>>>(N);
    count_deg_kernel<<<(E + 255) / 256, 256>>>(ei, E);
    scan1_kernel<<<nb, 256>>>(N);
    scan3_kernel<<<nb, 256>>>(N, nb);
    fill_csr_kernel<<<(E + 255) / 256, 256>>>(ei, E);

    // conv1: x -> hs ; gather -> aggA
    gemm_conv_kernel<<<gemm_blocks, 256, GEMM_SMEM>>>(x, W1, b1 /*unused*/, N, 0);
    gather_kernel<<<gath_blocks, 256>>>(N, 0);

    // conv2: relu(dinv*aggA + b1) -> hs ; gather -> aggB
    gemm_conv_kernel<<<gemm_blocks, 256, GEMM_SMEM>>>(x, W2, b1, N, 1);
    gather_kernel<<<gath_blocks, 256>>>(N, 1);

    // heads
    gemm_final_kernel<<<gemm_blocks, 256, GEMM_SMEM>>>(Wmu, Wlv, bmu, blv, b2, out, N);
}

// round 9
// speedup vs baseline: 1.1368x; 1.1368x over previous
#include <cuda_runtime.h>
#include <cuda_bf16.h>
#include <cstdint>

// ---------------------------------------------------------------------------
// GCN VGAE encoder (fp32, f32x2 FFMA 64x128-tile GEMMs, CSR gather 1 warp/node)
//   dinv = rsqrt(indeg+1)
//   GEMM:   hs = X@W                   (raw, no scaling -> independent of CSR)
//   gather: agg[v] = dinv[v]*hs[v] + sum_in dinv[s]*hs[s]
//   stage (fused in consumer GEMM): x = relu(dinv[v]*agg[v] + b)
//   heads:  [mu|lv] = x @ [Wmu|Wlv] + bias
// CSR build overlapped with GEMM1 via capture fork/join on a second stream.
// ---------------------------------------------------------------------------

#define MAXN 50000
#define MAXE 800000
#define FDIM 128

__device__ float g_dinv[MAXN];
__device__ int   g_degi[MAXN];
__device__ int   g_off [MAXN + 1];
__device__ int   g_cur [MAXN];
__device__ int   g_csr [MAXE];
__device__ int   g_bsum[256];
__device__ float g_hs  [MAXN * FDIM];
__device__ float g_aggA[MAXN * FDIM];
__device__ float g_aggB[MAXN * FDIM];

typedef unsigned long long ull;

#define SPLAT2(d, x) asm("mov.b64 %0, {%1, %1};" : "=l"(d) : "f"(x))
#define FMA2(d, a, b, c) \
    asm("fma.rn.f32x2 %0, %1, %2, %3;" : "=l"(d) : "l"(a), "l"(b), "l"(c))
#define UNPACK2(lo, hi, v) \
    asm("mov.b64 {%0, %1}, %2;" : "=f"(lo), "=f"(hi) : "l"(v))

// ======================= degree + CSR build =======================

__global__ void count_deg_kernel(const int* __restrict__ ei, int E) {
    int e = blockIdx.x * blockDim.x + threadIdx.x;
    if (e < E) atomicAdd(&g_degi[ei[E + e]], 1);
}

__global__ void scan1_kernel(int N) {
    __shared__ int s[256];
    int t = threadIdx.x;
    int i = blockIdx.x * 256 + t;
    s[t] = (i < N) ? g_degi[i] : 0;
    __syncthreads();
#pragma unroll
    for (int d = 128; d > 0; d >>= 1) {
        if (t < d) s[t] += s[t + d];
        __syncthreads();
    }
    if (t == 0) g_bsum[blockIdx.x] = s[0];
}

// per-block scan with redundant block-sum scan -> off, cur, dinv
__global__ void scan3_kernel(int N, int nb) {
    __shared__ int bs[256];
    __shared__ int s[256];
    int t = threadIdx.x;

    int bv = (t < nb) ? g_bsum[t] : 0;
    bs[t] = bv;
    __syncthreads();
#pragma unroll
    for (int d = 1; d < 256; d <<= 1) {
        int v = (t >= d) ? bs[t - d] : 0;
        __syncthreads();
        bs[t] += v;
        __syncthreads();
    }
    int base = bs[blockIdx.x] - ((blockIdx.x < nb) ? g_bsum[blockIdx.x] : 0);

    int i = blockIdx.x * 256 + t;
    int deg = (i < N) ? g_degi[i] : 0;
    s[t] = deg;
    __syncthreads();
#pragma unroll
    for (int d = 1; d < 256; d <<= 1) {
        int v = (t >= d) ? s[t - d] : 0;
        __syncthreads();
        s[t] += v;
        __syncthreads();
    }
    if (i < N) {
        int off = base + s[t] - deg;
        g_off[i] = off;
        g_cur[i] = off;
        g_dinv[i] = rsqrtf((float)deg + 1.0f);
        if (i == N - 1) g_off[N] = off + deg;
    }
}

__global__ void fill_csr_kernel(const int* __restrict__ ei, int E) {
    int e = blockIdx.x * blockDim.x + threadIdx.x;
    if (e < E) {
        int d = ei[E + e];
        int pos = atomicAdd(&g_cur[d], 1);
        g_csr[pos] = ei[e];
    }
}

// ======================= GEMM machinery =======================
// 256 threads, tile 64 rows x 128 cols. tx=t&31 -> cols tx*4..+3 ;
// ty=t>>5 (8 warps) -> rows ty*8..+7. Ws[128][128] + Xs[64][128] = 96KB smem.

#define GEMM_SMEM ((128 * 128 + 64 * 128) * 4)

__device__ __forceinline__ void load_xtile(float* Xs, const float* __restrict__ src,
                                           const float* __restrict__ bias, int fuse,
                                           int rowBase, int N, int t) {
#pragma unroll
    for (int i = 0; i < 8; i++) {
        int idx = t + i * 256;
        int r = idx >> 5, c4 = idx & 31;
        int rg = rowBase + r;
        float4 v = make_float4(0.f, 0.f, 0.f, 0.f);
        if (rg < N) {
            v = ((const float4*)src)[(size_t)rg * 32 + c4];
            if (fuse) {
                float dv = g_dinv[rg];
                float4 bb = ((const float4*)bias)[c4];
                v.x = fmaxf(v.x * dv + bb.x, 0.f);
                v.y = fmaxf(v.y * dv + bb.y, 0.f);
                v.z = fmaxf(v.z * dv + bb.z, 0.f);
                v.w = fmaxf(v.w * dv + bb.w, 0.f);
            }
        }
        ((float4*)Xs)[idx] = v;
    }
}

__device__ __forceinline__ void mm_tile(const float* Ws, const float* Xs,
                                        int c0, int r0, ull acc[8][2]) {
#pragma unroll
    for (int i = 0; i < 8; i++) { acc[i][0] = 0ull; acc[i][1] = 0ull; }

#pragma unroll 2
    for (int k0 = 0; k0 < 128; k0 += 4) {
        float4 a[8];
#pragma unroll
        for (int i = 0; i < 8; i++)
            a[i] = *(const float4*)(Xs + (r0 + i) * 128 + k0);
#pragma unroll
        for (int kk = 0; kk < 4; kk++) {
            ulonglong2 w = *(const ulonglong2*)(Ws + (k0 + kk) * 128 + c0);
#pragma unroll
            for (int i = 0; i < 8; i++) {
                ull s;
                SPLAT2(s, ((const float*)&a[i])[kk]);
                FMA2(acc[i][0], s, w.x, acc[i][0]);
                FMA2(acc[i][1], s, w.y, acc[i][1]);
            }
        }
    }
}

// conv GEMM: hs = X@W (raw). stage0: X=xin; stage1: X=relu(dinv*aggA+bias)
__global__ void __launch_bounds__(256)
gemm_conv_kernel(const float* __restrict__ xin,
                 const float* __restrict__ W,
                 const float* __restrict__ bias,
                 int N, int stage) {
    extern __shared__ float sm[];
    float* Ws = sm;
    float* Xs = sm + 128 * 128;
    const int t = threadIdx.x;
    const float* src = (stage == 0) ? xin : (const float*)g_aggA;

#pragma unroll
    for (int i = 0; i < 16; i++) {
        int idx = t + i * 256;
        ((float4*)Ws)[idx] = ((const float4*)W)[idx];
    }
    const int rowBase = blockIdx.x * 64;
    load_xtile(Xs, src, bias, stage != 0, rowBase, N, t);
    __syncthreads();

    const int tx = t & 31, ty = t >> 5;
    const int c0 = tx * 4, r0 = ty * 8;
    ull acc[8][2];
    mm_tile(Ws, Xs, c0, r0, acc);

#pragma unroll
    for (int i = 0; i < 8; i++) {
        int r = rowBase + r0 + i;
        if (r < N) {
            float a0, a1, a2, a3;
            UNPACK2(a0, a1, acc[i][0]);
            UNPACK2(a2, a3, acc[i][1]);
            *(float4*)(g_hs + (size_t)r * 128 + c0) = make_float4(a0, a1, a2, a3);
        }
    }
}

// final GEMM: [mu|lv] = relu(dinv*aggB+b2) @ [Wmu|Wlv] + bias
__global__ void __launch_bounds__(256)
gemm_final_kernel(const float* __restrict__ Wmu,
                  const float* __restrict__ Wlv,
                  const float* __restrict__ bmu,
                  const float* __restrict__ blv,
                  const float* __restrict__ b2,
                  float* __restrict__ out,
                  int N) {
    extern __shared__ float sm[];
    float* Ws = sm;
    float* Xs = sm + 128 * 128;
    const int t = threadIdx.x;

#pragma unroll
    for (int i = 0; i < 16; i++) {
        int idx = t + i * 256;
        int k = idx >> 5;
        int cc4 = idx & 31;
        float4 v = (cc4 < 16) ? ((const float4*)Wmu)[k * 16 + cc4]
                              : ((const float4*)Wlv)[k * 16 + (cc4 - 16)];
        ((float4*)Ws)[idx] = v;
    }
    const int rowBase = blockIdx.x * 64;
    load_xtile(Xs, (const float*)g_aggB, b2, 1, rowBase, N, t);
    __syncthreads();

    const int tx = t & 31, ty = t >> 5;
    const int c0 = tx * 4, r0 = ty * 8;
    ull acc[8][2];
    mm_tile(Ws, Xs, c0, r0, acc);

    const bool is_mu = (c0 < 64);
    const int cl = is_mu ? c0 : (c0 - 64);
    float4 bs = is_mu ? *(const float4*)(bmu + cl) : *(const float4*)(blv + cl);
#pragma unroll
    for (int i = 0; i < 8; i++) {
        int r = rowBase + r0 + i;
        if (r < N) {
            float a0, a1, a2, a3;
            UNPACK2(a0, a1, acc[i][0]);
            UNPACK2(a2, a3, acc[i][1]);
            float* base = is_mu ? (out + (size_t)r * 64 + cl)
                                : (out + (size_t)N * 64 + (size_t)r * 64 + cl);
            *(float4*)base = make_float4(a0 + bs.x, a1 + bs.y, a2 + bs.z, a3 + bs.w);
        }
    }
}

// ==== gather: agg[v] = dinv[v]*hs[v] + sum_in dinv[s]*hs[s] (1 warp/node) ===

__global__ void gather_kernel(int N, int which) {
    int node = (blockIdx.x * blockDim.x + threadIdx.x) >> 5;
    int lane = threadIdx.x & 31;
    if (node >= N) return;
    float* agg = which ? g_aggB : g_aggA;

    const float4* hs4 = (const float4*)g_hs;
    float dv = g_dinv[node];
    float4 a = hs4[(size_t)node * 32 + lane];
    float4 acc = make_float4(a.x * dv, a.y * dv, a.z * dv, a.w * dv);

    int j = g_off[node];
    int end = g_off[node + 1];
    for (; j + 4 <= end; j += 4) {
        int s0 = g_csr[j], s1 = g_csr[j + 1], s2 = g_csr[j + 2], s3 = g_csr[j + 3];
        float d0 = g_dinv[s0], d1 = g_dinv[s1], d2 = g_dinv[s2], d3 = g_dinv[s3];
        float4 v0 = hs4[(size_t)s0 * 32 + lane];
        float4 v1 = hs4[(size_t)s1 * 32 + lane];
        float4 v2 = hs4[(size_t)s2 * 32 + lane];
        float4 v3 = hs4[(size_t)s3 * 32 + lane];
        acc.x += d0 * v0.x + d1 * v1.x + d2 * v2.x + d3 * v3.x;
        acc.y += d0 * v0.y + d1 * v1.y + d2 * v2.y + d3 * v3.y;
        acc.z += d0 * v0.z + d1 * v1.z + d2 * v2.z + d3 * v3.z;
        acc.w += d0 * v0.w + d1 * v1.w + d2 * v2.w + d3 * v3.w;
    }
    for (; j < end; j++) {
        int s = g_csr[j];
        float d = g_dinv[s];
        float4 v = hs4[(size_t)s * 32 + lane];
        acc.x += d * v.x; acc.y += d * v.y; acc.z += d * v.z; acc.w += d * v.w;
    }
    ((float4*)agg)[(size_t)node * 32 + lane] = acc;
}

// ======================= launch =======================

extern "C" void kernel_launch(void* const* d_in, const int* in_sizes, int n_in,
                              void* d_out, int out_size) {
    const float* x   = (const float*)d_in[0];
    const int*   ei  = (const int*)d_in[1];      // int32 edge_index [2, E]
    const float* W1  = (const float*)d_in[2];
    const float* b1  = (const float*)d_in[3];
    const float* W2  = (const float*)d_in[4];
    const float* b2  = (const float*)d_in[5];
    const float* Wmu = (const float*)d_in[6];
    const float* bmu = (const float*)d_in[7];
    const float* Wlv = (const float*)d_in[8];
    const float* blv = (const float*)d_in[9];
    float* out = (float*)d_out;

    const int N = in_sizes[0] / 128;
    const int E = in_sizes[1] / 2;

    cudaFuncSetAttribute(gemm_conv_kernel,
                         cudaFuncAttributeMaxDynamicSharedMemorySize, GEMM_SMEM);
    cudaFuncSetAttribute(gemm_final_kernel,
                         cudaFuncAttributeMaxDynamicSharedMemorySize, GEMM_SMEM);

    const int nb = (N + 255) / 256;               // <= 256 for N <= 65536
    const int gemm_blocks = (N + 63) / 64;
    const int gath_blocks = (N + 7) / 8;          // 1 warp/node, 8 warps/block

    void* degi_ptr = nullptr;
    cudaGetSymbolAddress(&degi_ptr, g_degi);

    // fork: CSR chain on s2 overlaps gemm1 on the main (legacy) stream
    cudaStream_t s2;
    cudaEvent_t evFork, evJoin;
    cudaStreamCreateWithFlags(&s2, cudaStreamNonBlocking);
    cudaEventCreateWithFlags(&evFork, cudaEventDisableTiming);
    cudaEventCreateWithFlags(&evJoin, cudaEventDisableTiming);

    cudaEventRecord(evFork, 0);
    cudaStreamWaitEvent(s2, evFork, 0);

    // --- stream s2: degree + CSR ---
    cudaMemsetAsync(degi_ptr, 0, (size_t)N * sizeof(int), s2);
    count_deg_kernel<<<(E + 255) / 256, 256, 0, s2>>>(ei, E);
    scan1_kernel<<<nb, 256, 0, s2>>>(N);
    scan3_kernel<<<nb, 256, 0, s2>>>(N, nb);
    fill_csr_kernel<<<(E + 255) / 256, 256, 0, s2>>>(ei, E);
    cudaEventRecord(evJoin, s2);

    // --- main stream: gemm1 (independent of CSR/dinv) ---
    gemm_conv_kernel<<<gemm_blocks, 256, GEMM_SMEM>>>(x, W1, b1 /*unused*/, N, 0);

    // join: gather needs CSR + dinv
    cudaStreamWaitEvent(0, evJoin, 0);

    gather_kernel<<<gath_blocks, 256>>>(N, 0);
    gemm_conv_kernel<<<gemm_blocks, 256, GEMM_SMEM>>>(x, W2, b1, N, 1);
    gather_kernel<<<gath_blocks, 256>>>(N, 1);
    gemm_final_kernel<<<gemm_blocks, 256, GEMM_SMEM>>>(Wmu, Wlv, bmu, blv, b2, out, N);

    cudaEventDestroy(evFork);
    cudaEventDestroy(evJoin);
    cudaStreamDestroy(s2);
}